// round 14
// baseline (speedup 1.0000x reference)
#include <cuda_runtime.h>
#include <cuda_fp16.h>
#include <math.h>
#include <stdint.h>

#define BC        1024       // 8 * 128 merged batch*channel
#define LIN       65536
#define LOUT      16384
#define KNB       9
#define CHUNK_BC  256        // bc per pipeline chunk
#define NCHUNK    (BC / CHUNK_BC)          // 4
#define CHUNK_EL  ((size_t)LIN * CHUNK_BC) // halves per chunk buffer (32 MB)

#define GLT       64                        // l per gather CTA
#define GSUB      (CHUNK_BC / 64)           // 4
#define GGRID     ((LOUT / GLT) * GSUB)     // 1024 gather CTAs per chunk
#define TGRID     ((LIN / 64) * (CHUNK_BC / 64))   // 4096 transpose CTAs per chunk

// 64 MB ping-pong scratch, mostly L2-resident: buf[p][i][bcp], bcp < 256
__device__ __half g_buf[2 * CHUNK_EL];

// ---------------------------------------------------------------------------
// Combined kernel: gather of chunk gc (reads buf[gc&1]) + transpose of chunk
// tc (writes buf[tc&1]). Gather CTAs take the LOW blockIdx range.
// Transpose is SMEM-FREE: fp32->fp16 convert in regs, partner exchange via
// shfl.xor(4) (rows r and r^1), byte_perm to form (even,odd) bc-pair half2s,
// direct STG to scratch.
// ---------------------------------------------------------------------------
__global__ __launch_bounds__(256) void pool_kernel(const float* __restrict__ x,
                                                   const int*   __restrict__ nb,
                                                   float*       __restrict__ out,
                                                   int gc, int tc) {
    __shared__ __align__(16) __half s_out[64 * 66];   // gather staging, 8.4 KB

    const int t    = threadIdx.x;
    const int w    = t >> 5;
    const int lane = t & 31;
    const int gN   = (gc >= 0) ? GGRID : 0;

    if ((int)blockIdx.x < gN) {
        // ================= GATHER: chunk gc =================
        // CTA = (l tile of 64) x (64-bc sub-slice). lane gathers half2 ->
        // warp load = 128B fully-used. 9 loads batched per l, tree-reduce.
        const int gidx  = blockIdx.x;
        const int lTile = gidx >> 2;
        const int sub   = gidx & 3;
        const int lBase = lTile * GLT;

        // warp owns 8 l's; lanes 0-7 hold index columns (others mirror)
        int myIdx[KNB];
        const int myL = lBase + w * 8 + (lane & 7);
        #pragma unroll
        for (int k = 0; k < KNB; k++)
            myIdx[k] = __ldg(nb + (size_t)k * LOUT + myL);

        const __half2* xb = (const __half2*)(g_buf + (size_t)(gc & 1) * CHUNK_EL)
                            + sub * 32 + lane;

        #pragma unroll 1
        for (int m = 0; m < 8; m += 4) {
            __half2 acc[4];
            #pragma unroll
            for (int j = 0; j < 4; j++) {
                __half2 v[KNB];
                #pragma unroll
                for (int k = 0; k < KNB; k++) {
                    int i = __shfl_sync(0xffffffffu, myIdx[k], m + j);
                    v[k] = __ldg(xb + (size_t)i * 128);   // row stride 256 halves
                }
                __half2 m01 = __hmax2(v[0], v[1]);
                __half2 m23 = __hmax2(v[2], v[3]);
                __half2 m45 = __hmax2(v[4], v[5]);
                __half2 m67 = __hmax2(v[6], v[7]);
                m01 = __hmax2(m01, m23);
                m45 = __hmax2(m45, m67);
                acc[j] = __hmax2(__hmax2(m01, m45), v[8]);
            }
            const int ll = w * 8 + m;
            __half2* so = (__half2*)s_out;
            #pragma unroll
            for (int j = 0; j < 4; j++)
                so[(ll + j) * 33 + lane] = acc[j];   // bank (ll+j+lane)%32: free
        }
        __syncthreads();

        // writeback: t -> l = t&63, bc group (t>>6)*16; 128B coalesced stores
        const int l = t & 63;
        const int g = (t >> 6) * 16;
        float* ob = out + (size_t)(gc * CHUNK_BC + sub * 64 + g) * LOUT + lBase + l;
        #pragma unroll
        for (int b = 0; b < 16; b++)
            __stcs(ob + (size_t)b * LOUT, __half2float(s_out[l * 66 + g + b]));

    } else if (tc >= 0) {
        // ================= TRANSPOSE: chunk tc (smem-free) =================
        const int tidx   = blockIdx.x - gN;
        const int iBase  = (tidx >> 2) * 64;
        const int bcT    = tidx & 3;

        const int r = t >> 2;          // bc row in tile, 0..63
        const int q = t & 3;           // i quarter
        const bool rodd = (r & 1);

        // load 4 coalesced float4: i = 4q + 16m (+0..3); warp granule = 64B
        const float4* x4 = (const float4*)(x +
            (size_t)(tc * CHUNK_BC + bcT * 64 + r) * LIN + iBase) + q;
        float4 f[4];
        #pragma unroll
        for (int m = 0; m < 4; m++)
            f[m] = __ldcs(x4 + 4 * m);

        // convert: wj01[m] = (h(j0), h(j1)), wj23[m] = (h(j2), h(j3))
        uint32_t wj01[4], wj23[4];
        #pragma unroll
        for (int m = 0; m < 4; m++) {
            __half2 a = __floats2half2_rn(f[m].x, f[m].y);
            __half2 b = __floats2half2_rn(f[m].z, f[m].w);
            wj01[m] = *(uint32_t*)&a;
            wj23[m] = *(uint32_t*)&b;
        }

        // exchange with partner row r^1 (thread t^4): even gives j23, odd gives j01
        uint32_t recv[4];
        #pragma unroll
        for (int m = 0; m < 4; m++) {
            uint32_t give = rodd ? wj01[m] : wj23[m];
            recv[m] = __shfl_xor_sync(0xffffffffu, give, 4);
        }

        // scratch: half2 row = 128 per i; this thread's bc-pair = bcT*32 + r/2
        __half2* dst = (__half2*)(g_buf + (size_t)(tc & 1) * CHUNK_EL)
                       + bcT * 32 + (r >> 1);
        #pragma unroll
        for (int m = 0; m < 4; m++) {
            const size_t ib = (size_t)(iBase + 4 * q + 16 * m) * 128;
            if (!rodd) {
                // owns j0,j1: pair = (my h, partner h)
                uint32_t o0 = __byte_perm(wj01[m], recv[m], 0x5410);
                uint32_t o1 = __byte_perm(wj01[m], recv[m], 0x7632);
                dst[ib]       = *(__half2*)&o0;
                dst[ib + 128] = *(__half2*)&o1;
            } else {
                // owns j2,j3: pair = (partner h, my h)
                uint32_t o2 = __byte_perm(wj23[m], recv[m], 0x1054);
                uint32_t o3 = __byte_perm(wj23[m], recv[m], 0x3276);
                dst[ib + 256] = *(__half2*)&o2;
                dst[ib + 384] = *(__half2*)&o3;
            }
        }
    }
}

// ---------------------------------------------------------------------------
extern "C" void kernel_launch(void* const* d_in, const int* in_sizes, int n_in,
                              void* d_out, int out_size) {
    const float* x   = (const float*)d_in[0];
    const int*   nb  = (const int*)d_in[1];
    float*       out = (float*)d_out;

    (void)in_sizes; (void)n_in; (void)out_size;

    pool_kernel<<<TGRID, 256>>>(x, nb, out, -1, 0);                    // T0
    for (int c = 0; c < NCHUNK - 1; c++)
        pool_kernel<<<GGRID + TGRID, 256>>>(x, nb, out, c, c + 1);     // Gc || Tc+1
    pool_kernel<<<GGRID, 256>>>(x, nb, out, NCHUNK - 1, -1);           // G_last
}

// round 15
// speedup vs baseline: 1.0758x; 1.0758x over previous
#include <cuda_runtime.h>
#include <cuda_fp16.h>
#include <math.h>
#include <stdint.h>

#define BC        1024       // 8 * 128 merged batch*channel
#define LIN       65536
#define LOUT      16384
#define KNB       9
#define CHUNK_BC  256        // bc per pipeline chunk
#define NCHUNK    (BC / CHUNK_BC)          // 4
#define CHUNK_EL  ((size_t)LIN * CHUNK_BC) // halves per chunk buffer (32 MB)

#define GLT       64                        // l per gather CTA
#define GSUB      (CHUNK_BC / 64)           // 4
#define GGRID     ((LOUT / GLT) * GSUB)     // 1024 gather CTAs per chunk
#define TGRID     ((LIN / 64) * (CHUNK_BC / 64))   // 4096 transpose CTAs per chunk

// smem sub-tile bases: blk(rblk, cblk) = cblk*2120 + rblk*1057 floats.
// 1057 = 32*33 + 1: shifts row-block 1 by +1 bank so the store-phase LDS
// pattern (even rows lanes 0-15, base+1 rows lanes 16-31) covers 32 banks.
#define CBSTRIDE  2120
#define RBSTRIDE  1057
#define SMEM_WORDS (CBSTRIDE + RBSTRIDE + 31*33 + 31 + 1)   // 4232 floats

// 64 MB ping-pong scratch, mostly L2-resident: buf[p][i][bcp], bcp < 256
__device__ __half g_buf[2 * CHUNK_EL];

// ---------------------------------------------------------------------------
// Combined kernel: gather of chunk gc (reads buf[gc&1]) + transpose of chunk
// tc (writes buf[tc&1]). Gather CTAs take the LOW blockIdx range (first wave,
// L2 still warm with buf[gc] from the previous launch's transpose).
// ---------------------------------------------------------------------------
__global__ __launch_bounds__(256) void pool_kernel(const float* __restrict__ x,
                                                   const int*   __restrict__ nb,
                                                   float*       __restrict__ out,
                                                   int gc, int tc) {
    __shared__ __align__(16) float sm_raw[SMEM_WORDS];   // 16.9 KB (gather uses 8.4 KB)

    const int t    = threadIdx.x;
    const int w    = t >> 5;
    const int lane = t & 31;
    const int gN   = (gc >= 0) ? GGRID : 0;

    if ((int)blockIdx.x < gN) {
        // ================= GATHER: chunk gc =================
        // CTA = (l tile of 64) x (64-bc sub-slice). lane gathers half2 ->
        // warp load = 128B fully-used. 9 loads batched per l, tree-reduce.
        __half* s_out = (__half*)sm_raw;               // [64][66] = 8.4 KB

        const int gidx  = blockIdx.x;
        const int lTile = gidx >> 2;
        const int sub   = gidx & 3;
        const int lBase = lTile * GLT;

        // warp owns 8 l's; lanes 0-7 hold index columns (others mirror)
        int myIdx[KNB];
        const int myL = lBase + w * 8 + (lane & 7);
        #pragma unroll
        for (int k = 0; k < KNB; k++)
            myIdx[k] = __ldg(nb + (size_t)k * LOUT + myL);

        const __half2* xb = (const __half2*)(g_buf + (size_t)(gc & 1) * CHUNK_EL)
                            + sub * 32 + lane;

        #pragma unroll 1
        for (int m = 0; m < 8; m += 4) {
            __half2 acc[4];
            #pragma unroll
            for (int j = 0; j < 4; j++) {
                __half2 v[KNB];
                #pragma unroll
                for (int k = 0; k < KNB; k++) {
                    int i = __shfl_sync(0xffffffffu, myIdx[k], m + j);
                    v[k] = __ldg(xb + (size_t)i * 128);   // row stride 256 halves
                }
                __half2 m01 = __hmax2(v[0], v[1]);
                __half2 m23 = __hmax2(v[2], v[3]);
                __half2 m45 = __hmax2(v[4], v[5]);
                __half2 m67 = __hmax2(v[6], v[7]);
                m01 = __hmax2(m01, m23);
                m45 = __hmax2(m45, m67);
                acc[j] = __hmax2(__hmax2(m01, m45), v[8]);
            }
            const int ll = w * 8 + m;
            __half2* so = (__half2*)s_out;
            #pragma unroll
            for (int j = 0; j < 4; j++)
                so[(ll + j) * 33 + lane] = acc[j];   // bank (ll+j+lane)%32: free
        }
        __syncthreads();

        // writeback: t -> l = t&63, bc group (t>>6)*16; 128B coalesced stores
        const int l = t & 63;
        const int g = (t >> 6) * 16;
        float* ob = out + (size_t)(gc * CHUNK_BC + sub * 64 + g) * LOUT + lBase + l;
        #pragma unroll
        for (int b = 0; b < 16; b++)
            __stcs(ob + (size_t)b * LOUT, __half2float(s_out[l * 66 + g + b]));

    } else if (tc >= 0) {
        // ================= TRANSPOSE: chunk tc =================
        // Tile 64 bc x 64 i as four 32x33 fp32 sub-tiles; STS and both LDS
        // phases are fully conflict-free (see base-offset comment above).
        const int tidx   = blockIdx.x - gN;
        const int iBase  = (tidx >> 2) * 64;
        const int bcT    = tidx & 3;
        const int bcBase = tc * CHUNK_BC + bcT * 64;

        // ---- load: warp w owns bc rows w*8..w*8+7; per row 2 x LDG.32
        // (coalesced 128B) into sub-tiles. STS bank = (rr + lane)%32: free.
        #pragma unroll
        for (int u = 0; u < 8; u++) {
            int r    = w * 8 + u;           // 0..63
            int rblk = r >> 5, rr = r & 31;
            const float* xrow = x + (size_t)(bcBase + r) * LIN + iBase;
            #pragma unroll
            for (int cb = 0; cb < 2; cb++) {
                float v = __ldcs(xrow + cb * 32 + lane);
                sm_raw[cb * CBSTRIDE + rblk * RBSTRIDE + rr * 33 + lane] = v;
            }
        }
        __syncthreads();

        // ---- store: warp w owns i = w*8..w*8+7; lane = bc-pair.
        // LDS even: lanes 0-15 banks (2l+ii) even, lanes 16-31 (+1 base) odd
        // -> 32 distinct. LDS odd: symmetric. STG: 128B contiguous per i.
        const int rblk = lane >> 4;
        const int rr_e = (2 * lane) & 31;
        const int rr_o = (2 * lane + 1) & 31;
        __half2* dst = (__half2*)(g_buf + (size_t)(tc & 1) * CHUNK_EL)
                       + bcT * 32 + lane;
        #pragma unroll
        for (int s = 0; s < 8; s++) {
            int i  = w * 8 + s;             // 0..63
            int cb = i >> 5, ii = i & 31;
            const float* base = sm_raw + cb * CBSTRIDE + rblk * RBSTRIDE;
            float ve = base[rr_e * 33 + ii];
            float vo = base[rr_o * 33 + ii];
            dst[(size_t)(iBase + i) * 128] = __floats2half2_rn(ve, vo);
        }
    }
}

// ---------------------------------------------------------------------------
extern "C" void kernel_launch(void* const* d_in, const int* in_sizes, int n_in,
                              void* d_out, int out_size) {
    const float* x   = (const float*)d_in[0];
    const int*   nb  = (const int*)d_in[1];
    float*       out = (float*)d_out;

    (void)in_sizes; (void)n_in; (void)out_size;

    pool_kernel<<<TGRID, 256>>>(x, nb, out, -1, 0);                    // T0
    for (int c = 0; c < NCHUNK - 1; c++)
        pool_kernel<<<GGRID + TGRID, 256>>>(x, nb, out, c, c + 1);     // Gc || Tc+1
    pool_kernel<<<GGRID, 256>>>(x, nb, out, NCHUNK - 1, -1);           // G_last
}